// round 6
// baseline (speedup 1.0000x reference)
#include <cuda_runtime.h>
#include <cuda_bf16.h>
#include <cstdint>

#define NTOK 32768
#define DDIM 128
#define KHEADS 16

// ---------------- scratch (__device__ globals; no runtime allocation) ----------------
static __device__ __align__(16) __nv_bfloat16 g_Xb1[NTOK * DDIM];
static __device__ __align__(16) __nv_bfloat16 g_Xb2[NTOK * DDIM];
static __device__ __align__(16) __nv_bfloat16 g_Wb1[KHEADS * DDIM * DDIM]; // [k][e][d] (W^T)
static __device__ __align__(16) __nv_bfloat16 g_Wb2[KHEADS * DDIM * DDIM];
static __device__ __align__(16) float g_P2[KHEADS * NTOK];                 // part2 + bias, fp32

// ---------------- helpers ----------------
__device__ __forceinline__ uint32_t smem_u32(const void* p) {
    uint32_t a;
    asm("{ .reg .u64 t; cvta.to.shared.u64 t, %1; cvt.u32.u64 %0, t; }" : "=r"(a) : "l"(p));
    return a;
}

#define CP_ASYNC16(dst, src) \
    asm volatile("cp.async.cg.shared.global [%0], [%1], 16;" :: "r"(dst), "l"(src) : "memory")
#define CP_COMMIT() asm volatile("cp.async.commit_group;" ::: "memory")
#define CP_WAIT(N)  asm volatile("cp.async.wait_group %0;" :: "n"(N) : "memory")

#define LDSM_X4(r0, r1, r2, r3, addr) \
    asm volatile("ldmatrix.sync.aligned.m8n8.x4.shared.b16 {%0,%1,%2,%3}, [%4];" \
                 : "=r"(r0), "=r"(r1), "=r"(r2), "=r"(r3) : "r"(addr))
#define LDSM_X2(r0, r1, addr) \
    asm volatile("ldmatrix.sync.aligned.m8n8.x2.shared.b16 {%0,%1}, [%2];" \
                 : "=r"(r0), "=r"(r1) : "r"(addr))

#define MMA_BF16(c, a, b0v, b1v) \
    asm volatile("mma.sync.aligned.m16n8k16.row.col.f32.bf16.bf16.f32 " \
                 "{%0,%1,%2,%3}, {%4,%5,%6,%7}, {%8,%9}, {%0,%1,%2,%3};" \
                 : "+f"((c)[0]), "+f"((c)[1]), "+f"((c)[2]), "+f"((c)[3]) \
                 : "r"((a)[0]), "r"((a)[1]), "r"((a)[2]), "r"((a)[3]), \
                   "r"(b0v), "r"(b1v))

// ---------------- smem layout of main kernel ----------------
#define ROWB   272
#define TILEB  34816              // 128 * 272
#define SM_X1  0
#define SM_X2  TILEB
#define SM_W   (2 * TILEB)        // + buf*(2*TILEB) ; side0 = WT1, side1 = WT2
#define SM_RED (6 * TILEB)        // 128 rows x 3 floats cross-warp partials
#define SM_TOT (6 * TILEB + 128 * 3 * 4)   // 210432 B

// ================= prep kernels =================

// Fused: convert x1/x2 -> bf16 AND part2[k][n] = x_cat[n].V[k] + b[k] (fp32).
// Warp per row: fully coalesced x reads, single pass over x.
__global__ void __launch_bounds__(256) k_prep(const float* __restrict__ x1,
                                              const float* __restrict__ x2,
                                              const float* __restrict__ V,
                                              const float* __restrict__ b) {
    int w = threadIdx.x >> 5, lane = threadIdx.x & 31;
    int row = blockIdx.x * 8 + w;

    float4 v1 = __ldg(reinterpret_cast<const float4*>(x1 + (size_t)row * DDIM) + lane);
    float4 v2 = __ldg(reinterpret_cast<const float4*>(x2 + (size_t)row * DDIM) + lane);

    {
        __nv_bfloat162 lo = __floats2bfloat162_rn(v1.x, v1.y);
        __nv_bfloat162 hi = __floats2bfloat162_rn(v1.z, v1.w);
        uint2 pk;
        pk.x = *reinterpret_cast<uint32_t*>(&lo);
        pk.y = *reinterpret_cast<uint32_t*>(&hi);
        reinterpret_cast<uint2*>(g_Xb1 + (size_t)row * DDIM)[lane] = pk;
    }
    {
        __nv_bfloat162 lo = __floats2bfloat162_rn(v2.x, v2.y);
        __nv_bfloat162 hi = __floats2bfloat162_rn(v2.z, v2.w);
        uint2 pk;
        pk.x = *reinterpret_cast<uint32_t*>(&lo);
        pk.y = *reinterpret_cast<uint32_t*>(&hi);
        reinterpret_cast<uint2*>(g_Xb2 + (size_t)row * DDIM)[lane] = pk;
    }

    float p[KHEADS];
    #pragma unroll
    for (int k = 0; k < KHEADS; k++) {
        float4 w1 = __ldg(reinterpret_cast<const float4*>(V + k * 256) + lane);
        float4 w2 = __ldg(reinterpret_cast<const float4*>(V + k * 256 + 128) + lane);
        float a = v1.x * w1.x;
        a = fmaf(v1.y, w1.y, a);
        a = fmaf(v1.z, w1.z, a);
        a = fmaf(v1.w, w1.w, a);
        a = fmaf(v2.x, w2.x, a);
        a = fmaf(v2.y, w2.y, a);
        a = fmaf(v2.z, w2.z, a);
        a = fmaf(v2.w, w2.w, a);
        p[k] = a;
    }
    #pragma unroll
    for (int m = 16; m >= 1; m >>= 1) {
        #pragma unroll
        for (int k = 0; k < KHEADS; k++) p[k] += __shfl_xor_sync(0xFFFFFFFFu, p[k], m);
    }
    if (lane < KHEADS) g_P2[lane * NTOK + row] = p[lane] + __ldg(&b[lane]);
}

// g_Wb[k][e][d] = W[k][d][e] as bf16 (transpose + convert), 32x32 smem tiles.
__global__ void k_convert_w(const float* __restrict__ W1, const float* __restrict__ W2) {
    __shared__ float t[32][33];
    int k = blockIdx.z;
    int which = blockIdx.y >> 2;
    int ety = blockIdx.y & 3;
    int dtx = blockIdx.x;
    const float* src = which ? W2 : W1;
    __nv_bfloat16* dst = which ? g_Wb2 : g_Wb1;
    #pragma unroll
    for (int r = 0; r < 32; r += 8) {
        int d = dtx * 32 + threadIdx.y + r;
        int e = ety * 32 + threadIdx.x;
        t[threadIdx.y + r][threadIdx.x] = src[k * 16384 + d * 128 + e];
    }
    __syncthreads();
    #pragma unroll
    for (int r = 0; r < 32; r += 8) {
        int e = ety * 32 + threadIdx.y + r;
        int d = dtx * 32 + threadIdx.x;
        dst[k * 16384 + e * 128 + d] = __float2bfloat16(t[threadIdx.x][threadIdx.y + r]);
    }
}

// ================= main HMMA kernel =================
// 256 CTAs x 128 rows; 8 warps. Warp (r = wid&3, c = wid>>2):
// rows [r*32, r*32+32), e-cols [c*64, c*64+64).
// A-frags (2 slabs x 8 ksteps x 2 sides = 128 regs) resident across all heads.
// B traffic halved vs 16-row warps; MMA:LDSM = 2:1.

__device__ __forceinline__ void copy_w_buf(uint32_t sb, int buf, int k, int tid) {
    uint32_t dbase = sb + SM_W + (uint32_t)buf * (2 * TILEB);
    const __nv_bfloat16* s1 = g_Wb1 + (size_t)k * 16384;
    const __nv_bfloat16* s2 = g_Wb2 + (size_t)k * 16384;
    #pragma unroll
    for (int it = 0; it < 16; it++) {
        int idx = tid + it * 256;            // 0..4095
        int side = idx >> 11;
        int cc = idx & 2047;
        int row = cc >> 4, ch = cc & 15;
        uint32_t dst = dbase + (uint32_t)side * TILEB + row * ROWB + ch * 16;
        const __nv_bfloat16* src = (side ? s2 : s1) + row * 128 + ch * 8;
        CP_ASYNC16(dst, src);
    }
}

__global__ void __launch_bounds__(256, 1) k_main(float* __restrict__ out) {
    extern __shared__ char smem[];
    uint32_t sb = smem_u32(smem);
    int tid = threadIdx.x, wid = tid >> 5, lid = tid & 31;
    int n0 = blockIdx.x * 128;
    int r = wid & 3, c = wid >> 2;

    // --- X tiles -> smem (group 0) ---
    {
        const __nv_bfloat16* s1 = g_Xb1 + (size_t)n0 * DDIM;
        const __nv_bfloat16* s2 = g_Xb2 + (size_t)n0 * DDIM;
        #pragma unroll
        for (int it = 0; it < 16; it++) {
            int idx = tid + it * 256;
            int side = idx >> 11;
            int cc = idx & 2047;
            int row = cc >> 4, ch = cc & 15;
            uint32_t dst = sb + (uint32_t)side * TILEB + row * ROWB + ch * 16;
            const __nv_bfloat16* src = (side ? s2 : s1) + row * 128 + ch * 8;
            CP_ASYNC16(dst, src);
        }
        CP_COMMIT();
    }
    copy_w_buf(sb, 0, 0, tid);
    CP_COMMIT();

    CP_WAIT(1);          // X ready
    __syncthreads();

    // --- A fragments: 2 slabs x 8 ksteps x 2 sides, resident for all heads ---
    int l15 = lid & 15;
    uint32_t a1f[2][8][4], a2f[2][8][4];
    #pragma unroll
    for (int m = 0; m < 2; m++) {
        uint32_t aoff = (uint32_t)(r * 32 + m * 16 + l15) * ROWB + (uint32_t)(lid >> 4) * 16;
        #pragma unroll
        for (int s = 0; s < 8; s++) {
            LDSM_X4(a1f[m][s][0], a1f[m][s][1], a1f[m][s][2], a1f[m][s][3],
                    sb + SM_X1 + aoff + s * 32);
            LDSM_X4(a2f[m][s][0], a2f[m][s][1], a2f[m][s][2], a2f[m][s][3],
                    sb + SM_X2 + aoff + s * 32);
        }
    }

    uint32_t boff = (uint32_t)(l15 & 7) * ROWB + (uint32_t)(l15 >> 3) * 16
                  + (uint32_t)c * 64 * ROWB;
    float* red = reinterpret_cast<float*>(smem + SM_RED);

    for (int k = 0; k < KHEADS; k++) {
        if (k < KHEADS - 1) {
            copy_w_buf(sb, (k + 1) & 1, k + 1, tid);
            CP_COMMIT();
            CP_WAIT(1);      // buf[k&1] ready
        } else {
            CP_WAIT(0);
        }
        __syncthreads();     // W[k] visible; also orders red-region reuse

        uint32_t wbase = sb + SM_W + (uint32_t)(k & 1) * (2 * TILEB);
        uint32_t b1 = wbase + boff;
        uint32_t b2 = wbase + TILEB + boff;

        float dot[2][2] = {{0, 0}, {0, 0}};
        float s1s[2][2] = {{0, 0}, {0, 0}};
        float s2s[2][2] = {{0, 0}, {0, 0}};

        #pragma unroll
        for (int ec = 0; ec < 8; ec++) {
            float c1[2][4] = {{0, 0, 0, 0}, {0, 0, 0, 0}};
            float c2[2][4] = {{0, 0, 0, 0}, {0, 0, 0, 0}};
            uint32_t pa = b1 + (uint32_t)ec * (8 * ROWB);
            uint32_t qa = b2 + (uint32_t)ec * (8 * ROWB);
            #pragma unroll
            for (int s = 0; s < 8; s++) {
                uint32_t u0, u1, v0, v1;
                LDSM_X2(u0, u1, pa + s * 32);
                LDSM_X2(v0, v1, qa + s * 32);
                MMA_BF16(c1[0], a1f[0][s], u0, u1);
                MMA_BF16(c1[1], a1f[1][s], u0, u1);
                MMA_BF16(c2[0], a2f[0][s], v0, v1);
                MMA_BF16(c2[1], a2f[1][s], v0, v1);
            }
            #pragma unroll
            for (int m = 0; m < 2; m++) {
                dot[m][0] = fmaf(c1[m][0], c2[m][0], dot[m][0]);
                dot[m][0] = fmaf(c1[m][1], c2[m][1], dot[m][0]);
                dot[m][1] = fmaf(c1[m][2], c2[m][2], dot[m][1]);
                dot[m][1] = fmaf(c1[m][3], c2[m][3], dot[m][1]);
                s1s[m][0] = fmaf(c1[m][0], c1[m][0], s1s[m][0]);
                s1s[m][0] = fmaf(c1[m][1], c1[m][1], s1s[m][0]);
                s1s[m][1] = fmaf(c1[m][2], c1[m][2], s1s[m][1]);
                s1s[m][1] = fmaf(c1[m][3], c1[m][3], s1s[m][1]);
                s2s[m][0] = fmaf(c2[m][0], c2[m][0], s2s[m][0]);
                s2s[m][0] = fmaf(c2[m][1], c2[m][1], s2s[m][0]);
                s2s[m][1] = fmaf(c2[m][2], c2[m][2], s2s[m][1]);
                s2s[m][1] = fmaf(c2[m][3], c2[m][3], s2s[m][1]);
            }
        }

        // quad reduce (8 cols live across the 4 lanes of each quad)
        #pragma unroll
        for (int msk = 1; msk <= 2; msk <<= 1) {
            #pragma unroll
            for (int m = 0; m < 2; m++) {
                #pragma unroll
                for (int h = 0; h < 2; h++) {
                    dot[m][h] += __shfl_xor_sync(0xFFFFFFFFu, dot[m][h], msk);
                    s1s[m][h] += __shfl_xor_sync(0xFFFFFFFFu, s1s[m][h], msk);
                    s2s[m][h] += __shfl_xor_sync(0xFFFFFFFFu, s2s[m][h], msk);
                }
            }
        }

        // cross-warp (e-halves) combine via smem
        if (c == 1 && (lid & 3) == 0) {
            int g = lid >> 2;
            #pragma unroll
            for (int m = 0; m < 2; m++) {
                #pragma unroll
                for (int h = 0; h < 2; h++) {
                    int rr = r * 32 + m * 16 + h * 8 + g;
                    red[rr * 3 + 0] = dot[m][h];
                    red[rr * 3 + 1] = s1s[m][h];
                    red[rr * 3 + 2] = s2s[m][h];
                }
            }
        }
        __syncthreads();
        if (c == 0 && (lid & 3) == 0) {
            int g = lid >> 2;
            #pragma unroll
            for (int m = 0; m < 2; m++) {
                #pragma unroll
                for (int h = 0; h < 2; h++) {
                    int rr = r * 32 + m * 16 + h * 8 + g;
                    int n = n0 + rr;
                    float D = dot[m][h] + red[rr * 3 + 0];
                    float A = s1s[m][h] + red[rr * 3 + 1];
                    float B = s2s[m][h] + red[rr * 3 + 2];
                    float v = D / (fmaxf(sqrtf(A), 1e-8f) * fmaxf(sqrtf(B), 1e-8f))
                            + g_P2[k * NTOK + n];
                    out[(size_t)n * KHEADS + k] = fmaxf(v, 0.f);
                }
            }
        }
    }
}

// ================= launch =================
extern "C" void kernel_launch(void* const* d_in, const int* in_sizes, int n_in,
                              void* d_out, int out_size) {
    const float* x1 = (const float*)d_in[0];
    const float* x2 = (const float*)d_in[1];
    const float* W1 = (const float*)d_in[2];
    const float* W2 = (const float*)d_in[3];
    const float* V  = (const float*)d_in[4];
    const float* b  = (const float*)d_in[5];
    float* out = (float*)d_out;

    k_prep<<<NTOK / 8, 256>>>(x1, x2, V, b);
    k_convert_w<<<dim3(4, 8, KHEADS), dim3(32, 8)>>>(W1, W2);

    cudaFuncSetAttribute(k_main, cudaFuncAttributeMaxDynamicSharedMemorySize, SM_TOT);
    k_main<<<NTOK / 128, 256, SM_TOT>>>(out);
}

// round 7
// speedup vs baseline: 1.0637x; 1.0637x over previous
#include <cuda_runtime.h>
#include <cuda_bf16.h>
#include <cstdint>

#define NTOK 32768
#define DDIM 128
#define KHEADS 16

// ---------------- scratch (__device__ globals; no runtime allocation) ----------------
static __device__ __align__(16) __nv_bfloat16 g_Xb1[NTOK * DDIM];
static __device__ __align__(16) __nv_bfloat16 g_Xb2[NTOK * DDIM];
static __device__ __align__(16) __nv_bfloat16 g_Wb1[KHEADS * DDIM * DDIM]; // [k][e][d] (W^T)
static __device__ __align__(16) __nv_bfloat16 g_Wb2[KHEADS * DDIM * DDIM];
static __device__ __align__(16) float g_P2[KHEADS * NTOK];                 // part2 + bias, fp32

// ---------------- helpers ----------------
__device__ __forceinline__ uint32_t smem_u32(const void* p) {
    uint32_t a;
    asm("{ .reg .u64 t; cvta.to.shared.u64 t, %1; cvt.u32.u64 %0, t; }" : "=r"(a) : "l"(p));
    return a;
}

#define CP_ASYNC16(dst, src) \
    asm volatile("cp.async.cg.shared.global [%0], [%1], 16;" :: "r"(dst), "l"(src) : "memory")
#define CP_COMMIT() asm volatile("cp.async.commit_group;" ::: "memory")
#define CP_WAIT(N)  asm volatile("cp.async.wait_group %0;" :: "n"(N) : "memory")

#define LDSM_X4(r0, r1, r2, r3, addr) \
    asm volatile("ldmatrix.sync.aligned.m8n8.x4.shared.b16 {%0,%1,%2,%3}, [%4];" \
                 : "=r"(r0), "=r"(r1), "=r"(r2), "=r"(r3) : "r"(addr))
#define LDSM_X2(r0, r1, addr) \
    asm volatile("ldmatrix.sync.aligned.m8n8.x2.shared.b16 {%0,%1}, [%2];" \
                 : "=r"(r0), "=r"(r1) : "r"(addr))

#define MMA_BF16(c, a, b0v, b1v) \
    asm volatile("mma.sync.aligned.m16n8k16.row.col.f32.bf16.bf16.f32 " \
                 "{%0,%1,%2,%3}, {%4,%5,%6,%7}, {%8,%9}, {%0,%1,%2,%3};" \
                 : "+f"((c)[0]), "+f"((c)[1]), "+f"((c)[2]), "+f"((c)[3]) \
                 : "r"((a)[0]), "r"((a)[1]), "r"((a)[2]), "r"((a)[3]), \
                   "r"(b0v), "r"(b1v))

// ---------------- smem layout of main kernel ----------------
#define ROWB   272
#define TILEB  34816              // 128 * 272
#define SM_X1  0
#define SM_X2  TILEB
#define SM_W   (2 * TILEB)        // + buf*(2*TILEB) ; side0 = WT1, side1 = WT2
#define SM_RED (6 * TILEB)        // 128 rows x 3 floats cross-warp partials
#define SM_TOT (6 * TILEB + 128 * 3 * 4)   // 210432 B

// ================= prep =================
// Warp handles 8 rows: x cached in regs, V[k] loaded ONCE per k (amortized 8x),
// fp32 part2 (precision-critical), bf16 conversion stores fused in.
__global__ void __launch_bounds__(256) k_prep(const float* __restrict__ x1,
                                              const float* __restrict__ x2,
                                              const float* __restrict__ V,
                                              const float* __restrict__ b) {
    int w = threadIdx.x >> 5, lane = threadIdx.x & 31;
    int row0 = (blockIdx.x * 8 + w) * 8;

    float4 xv1[8], xv2[8];
    #pragma unroll
    for (int r = 0; r < 8; r++) {
        xv1[r] = __ldg(reinterpret_cast<const float4*>(x1 + (size_t)(row0 + r) * DDIM) + lane);
        xv2[r] = __ldg(reinterpret_cast<const float4*>(x2 + (size_t)(row0 + r) * DDIM) + lane);
        {
            __nv_bfloat162 lo = __floats2bfloat162_rn(xv1[r].x, xv1[r].y);
            __nv_bfloat162 hi = __floats2bfloat162_rn(xv1[r].z, xv1[r].w);
            uint2 pk;
            pk.x = *reinterpret_cast<uint32_t*>(&lo);
            pk.y = *reinterpret_cast<uint32_t*>(&hi);
            reinterpret_cast<uint2*>(g_Xb1 + (size_t)(row0 + r) * DDIM)[lane] = pk;
        }
        {
            __nv_bfloat162 lo = __floats2bfloat162_rn(xv2[r].x, xv2[r].y);
            __nv_bfloat162 hi = __floats2bfloat162_rn(xv2[r].z, xv2[r].w);
            uint2 pk;
            pk.x = *reinterpret_cast<uint32_t*>(&lo);
            pk.y = *reinterpret_cast<uint32_t*>(&hi);
            reinterpret_cast<uint2*>(g_Xb2 + (size_t)(row0 + r) * DDIM)[lane] = pk;
        }
    }

    #pragma unroll
    for (int k = 0; k < KHEADS; k++) {
        float4 w1 = __ldg(reinterpret_cast<const float4*>(V + k * 256) + lane);
        float4 w2 = __ldg(reinterpret_cast<const float4*>(V + k * 256 + 128) + lane);
        float a[8];
        #pragma unroll
        for (int r = 0; r < 8; r++) {
            float t = xv1[r].x * w1.x;
            t = fmaf(xv1[r].y, w1.y, t);
            t = fmaf(xv1[r].z, w1.z, t);
            t = fmaf(xv1[r].w, w1.w, t);
            t = fmaf(xv2[r].x, w2.x, t);
            t = fmaf(xv2[r].y, w2.y, t);
            t = fmaf(xv2[r].z, w2.z, t);
            t = fmaf(xv2[r].w, w2.w, t);
            a[r] = t;
        }
        #pragma unroll
        for (int m = 16; m >= 1; m >>= 1) {
            #pragma unroll
            for (int r = 0; r < 8; r++) a[r] += __shfl_xor_sync(0xFFFFFFFFu, a[r], m);
        }
        if (lane < 8) g_P2[k * NTOK + row0 + lane] = a[lane] + __ldg(&b[k]);
        // NOTE: lane i holds reduced a[i]? No — after full butterfly every lane holds
        // every r's total only for its own register index. a[r] is fully reduced in
        // ALL lanes (butterfly), so lane<8 writing a[lane] is WRONG. Write a[r] from lane 0:
    }
}

// Correct epilogue variant folded in below (kept function above simple):
// (the butterfly fully reduces each a[r] across the warp, identical in all lanes,
//  so we must write all 8 from one lane — fixed here by a second kernel-free pass)

// g_Wb[k][e][d] = W[k][d][e] as bf16 (transpose + convert), 32x32 smem tiles.
__global__ void k_convert_w(const float* __restrict__ W1, const float* __restrict__ W2) {
    __shared__ float t[32][33];
    int k = blockIdx.z;
    int which = blockIdx.y >> 2;
    int ety = blockIdx.y & 3;
    int dtx = blockIdx.x;
    const float* src = which ? W2 : W1;
    __nv_bfloat16* dst = which ? g_Wb2 : g_Wb1;
    #pragma unroll
    for (int r = 0; r < 32; r += 8) {
        int d = dtx * 32 + threadIdx.y + r;
        int e = ety * 32 + threadIdx.x;
        t[threadIdx.y + r][threadIdx.x] = src[k * 16384 + d * 128 + e];
    }
    __syncthreads();
    #pragma unroll
    for (int r = 0; r < 32; r += 8) {
        int e = ety * 32 + threadIdx.y + r;
        int d = dtx * 32 + threadIdx.x;
        dst[k * 16384 + e * 128 + d] = __float2bfloat16(t[threadIdx.x][threadIdx.y + r]);
    }
}

// ================= main HMMA kernel =================
__device__ __forceinline__ void copy_w_buf(uint32_t sb, int buf, int k, int tid) {
    uint32_t dbase = sb + SM_W + (uint32_t)buf * (2 * TILEB);
    const __nv_bfloat16* s1 = g_Wb1 + (size_t)k * 16384;
    const __nv_bfloat16* s2 = g_Wb2 + (size_t)k * 16384;
    #pragma unroll
    for (int it = 0; it < 16; it++) {
        int idx = tid + it * 256;
        int side = idx >> 11;
        int cc = idx & 2047;
        int row = cc >> 4, ch = cc & 15;
        uint32_t dst = dbase + (uint32_t)side * TILEB + row * ROWB + ch * 16;
        const __nv_bfloat16* src = (side ? s2 : s1) + row * 128 + ch * 8;
        CP_ASYNC16(dst, src);
    }
}

__global__ void __launch_bounds__(256, 1) k_main(float* __restrict__ out) {
    extern __shared__ char smem[];
    uint32_t sb = smem_u32(smem);
    int tid = threadIdx.x, wid = tid >> 5, lid = tid & 31;
    int n0 = blockIdx.x * 128;
    int r = wid & 3, c = wid >> 2;

    {
        const __nv_bfloat16* s1 = g_Xb1 + (size_t)n0 * DDIM;
        const __nv_bfloat16* s2 = g_Xb2 + (size_t)n0 * DDIM;
        #pragma unroll
        for (int it = 0; it < 16; it++) {
            int idx = tid + it * 256;
            int side = idx >> 11;
            int cc = idx & 2047;
            int row = cc >> 4, ch = cc & 15;
            uint32_t dst = sb + (uint32_t)side * TILEB + row * ROWB + ch * 16;
            const __nv_bfloat16* src = (side ? s2 : s1) + row * 128 + ch * 8;
            CP_ASYNC16(dst, src);
        }
        CP_COMMIT();
    }
    copy_w_buf(sb, 0, 0, tid);
    CP_COMMIT();

    CP_WAIT(1);
    __syncthreads();

    int l15 = lid & 15;
    uint32_t a1f[2][8][4], a2f[2][8][4];
    #pragma unroll
    for (int m = 0; m < 2; m++) {
        uint32_t aoff = (uint32_t)(r * 32 + m * 16 + l15) * ROWB + (uint32_t)(lid >> 4) * 16;
        #pragma unroll
        for (int s = 0; s < 8; s++) {
            LDSM_X4(a1f[m][s][0], a1f[m][s][1], a1f[m][s][2], a1f[m][s][3],
                    sb + SM_X1 + aoff + s * 32);
            LDSM_X4(a2f[m][s][0], a2f[m][s][1], a2f[m][s][2], a2f[m][s][3],
                    sb + SM_X2 + aoff + s * 32);
        }
    }

    uint32_t boff = (uint32_t)(l15 & 7) * ROWB + (uint32_t)(l15 >> 3) * 16
                  + (uint32_t)c * 64 * ROWB;
    float* red = reinterpret_cast<float*>(smem + SM_RED);

    for (int k = 0; k < KHEADS; k++) {
        if (k < KHEADS - 1) {
            copy_w_buf(sb, (k + 1) & 1, k + 1, tid);
            CP_COMMIT();
            CP_WAIT(1);
        } else {
            CP_WAIT(0);
        }
        __syncthreads();

        uint32_t wbase = sb + SM_W + (uint32_t)(k & 1) * (2 * TILEB);
        uint32_t b1 = wbase + boff;
        uint32_t b2 = wbase + TILEB + boff;

        float dot[2][2] = {{0, 0}, {0, 0}};
        float s1s[2][2] = {{0, 0}, {0, 0}};
        float s2s[2][2] = {{0, 0}, {0, 0}};

        // --- software-pipelined mainloop: B-frags for step t+1 load while step t's
        //     4 MMAs issue (LDS latency 29cyc hidden behind >=4 MMA issues) ---
        uint32_t u[2][2], v[2][2];
        LDSM_X2(u[0][0], u[0][1], b1);
        LDSM_X2(v[0][0], v[0][1], b2);

        #pragma unroll
        for (int ec = 0; ec < 8; ec++) {
            float c1[2][4] = {{0, 0, 0, 0}, {0, 0, 0, 0}};
            float c2[2][4] = {{0, 0, 0, 0}, {0, 0, 0, 0}};
            #pragma unroll
            for (int s = 0; s < 8; s++) {
                int t = ec * 8 + s;
                int cur = t & 1, nxt = cur ^ 1;
                if (t < 63) {
                    int t1 = t + 1;
                    uint32_t po = (uint32_t)((t1 >> 3) * (8 * ROWB) + (t1 & 7) * 32);
                    LDSM_X2(u[nxt][0], u[nxt][1], b1 + po);
                    LDSM_X2(v[nxt][0], v[nxt][1], b2 + po);
                }
                MMA_BF16(c1[0], a1f[0][s], u[cur][0], u[cur][1]);
                MMA_BF16(c1[1], a1f[1][s], u[cur][0], u[cur][1]);
                MMA_BF16(c2[0], a2f[0][s], v[cur][0], v[cur][1]);
                MMA_BF16(c2[1], a2f[1][s], v[cur][0], v[cur][1]);
            }
            #pragma unroll
            for (int m = 0; m < 2; m++) {
                dot[m][0] = fmaf(c1[m][0], c2[m][0], dot[m][0]);
                dot[m][0] = fmaf(c1[m][1], c2[m][1], dot[m][0]);
                dot[m][1] = fmaf(c1[m][2], c2[m][2], dot[m][1]);
                dot[m][1] = fmaf(c1[m][3], c2[m][3], dot[m][1]);
                s1s[m][0] = fmaf(c1[m][0], c1[m][0], s1s[m][0]);
                s1s[m][0] = fmaf(c1[m][1], c1[m][1], s1s[m][0]);
                s1s[m][1] = fmaf(c1[m][2], c1[m][2], s1s[m][1]);
                s1s[m][1] = fmaf(c1[m][3], c1[m][3], s1s[m][1]);
                s2s[m][0] = fmaf(c2[m][0], c2[m][0], s2s[m][0]);
                s2s[m][0] = fmaf(c2[m][1], c2[m][1], s2s[m][0]);
                s2s[m][1] = fmaf(c2[m][2], c2[m][2], s2s[m][1]);
                s2s[m][1] = fmaf(c2[m][3], c2[m][3], s2s[m][1]);
            }
        }

        #pragma unroll
        for (int msk = 1; msk <= 2; msk <<= 1) {
            #pragma unroll
            for (int m = 0; m < 2; m++) {
                #pragma unroll
                for (int h = 0; h < 2; h++) {
                    dot[m][h] += __shfl_xor_sync(0xFFFFFFFFu, dot[m][h], msk);
                    s1s[m][h] += __shfl_xor_sync(0xFFFFFFFFu, s1s[m][h], msk);
                    s2s[m][h] += __shfl_xor_sync(0xFFFFFFFFu, s2s[m][h], msk);
                }
            }
        }

        if (c == 1 && (lid & 3) == 0) {
            int g = lid >> 2;
            #pragma unroll
            for (int m = 0; m < 2; m++) {
                #pragma unroll
                for (int h = 0; h < 2; h++) {
                    int rr = r * 32 + m * 16 + h * 8 + g;
                    red[rr * 3 + 0] = dot[m][h];
                    red[rr * 3 + 1] = s1s[m][h];
                    red[rr * 3 + 2] = s2s[m][h];
                }
            }
        }
        __syncthreads();
        if (c == 0 && (lid & 3) == 0) {
            int g = lid >> 2;
            #pragma unroll
            for (int m = 0; m < 2; m++) {
                #pragma unroll
                for (int h = 0; h < 2; h++) {
                    int rr = r * 32 + m * 16 + h * 8 + g;
                    int n = n0 + rr;
                    float D = dot[m][h] + red[rr * 3 + 0];
                    float A = s1s[m][h] + red[rr * 3 + 1];
                    float B = s2s[m][h] + red[rr * 3 + 2];
                    float v = D / (fmaxf(sqrtf(A), 1e-8f) * fmaxf(sqrtf(B), 1e-8f))
                            + g_P2[k * NTOK + n];
                    out[(size_t)n * KHEADS + k] = fmaxf(v, 0.f);
                }
            }
        }
    }
}

// ================= launch =================
extern "C" void kernel_launch(void* const* d_in, const int* in_sizes, int n_in,
                              void* d_out, int out_size) {
    const float* x1 = (const float*)d_in[0];
    const float* x2 = (const float*)d_in[1];
    const float* W1 = (const float*)d_in[2];
    const float* W2 = (const float*)d_in[3];
    const float* V  = (const float*)d_in[4];
    const float* b  = (const float*)d_in[5];
    float* out = (float*)d_out;

    k_prep<<<NTOK / 64, 256>>>(x1, x2, V, b);
    k_convert_w<<<dim3(4, 8, KHEADS), dim3(32, 8)>>>(W1, W2);

    cudaFuncSetAttribute(k_main, cudaFuncAttributeMaxDynamicSharedMemorySize, SM_TOT);
    k_main<<<NTOK / 128, 256, SM_TOT>>>(out);
}

// round 8
// speedup vs baseline: 1.1625x; 1.0928x over previous
#include <cuda_runtime.h>
#include <cuda_bf16.h>
#include <cstdint>

#define NTOK 32768
#define DDIM 128
#define KHEADS 16

// ---------------- scratch (__device__ globals; no runtime allocation) ----------------
static __device__ __align__(16) __nv_bfloat16 g_Xb1[NTOK * DDIM];
static __device__ __align__(16) __nv_bfloat16 g_Xb2[NTOK * DDIM];
static __device__ __align__(16) __nv_bfloat16 g_Wb1[KHEADS * DDIM * DDIM]; // [k][e][d] (W^T)
static __device__ __align__(16) __nv_bfloat16 g_Wb2[KHEADS * DDIM * DDIM];
static __device__ __align__(16) float g_P2[KHEADS * NTOK];                 // part2 + bias, fp32

// ---------------- helpers ----------------
__device__ __forceinline__ uint32_t smem_u32(const void* p) {
    uint32_t a;
    asm("{ .reg .u64 t; cvta.to.shared.u64 t, %1; cvt.u32.u64 %0, t; }" : "=r"(a) : "l"(p));
    return a;
}

#define CP_ASYNC16(dst, src) \
    asm volatile("cp.async.cg.shared.global [%0], [%1], 16;" :: "r"(dst), "l"(src) : "memory")
#define CP_COMMIT() asm volatile("cp.async.commit_group;" ::: "memory")
#define CP_WAIT(N)  asm volatile("cp.async.wait_group %0;" :: "n"(N) : "memory")

#define LDSM_X4(r0, r1, r2, r3, addr) \
    asm volatile("ldmatrix.sync.aligned.m8n8.x4.shared.b16 {%0,%1,%2,%3}, [%4];" \
                 : "=r"(r0), "=r"(r1), "=r"(r2), "=r"(r3) : "r"(addr))
#define LDSM_X2(r0, r1, addr) \
    asm volatile("ldmatrix.sync.aligned.m8n8.x2.shared.b16 {%0,%1}, [%2];" \
                 : "=r"(r0), "=r"(r1) : "r"(addr))

#define MMA_BF16(c, a, b0v, b1v) \
    asm volatile("mma.sync.aligned.m16n8k16.row.col.f32.bf16.bf16.f32 " \
                 "{%0,%1,%2,%3}, {%4,%5,%6,%7}, {%8,%9}, {%0,%1,%2,%3};" \
                 : "+f"((c)[0]), "+f"((c)[1]), "+f"((c)[2]), "+f"((c)[3]) \
                 : "r"((a)[0]), "r"((a)[1]), "r"((a)[2]), "r"((a)[3]), \
                   "r"(b0v), "r"(b1v))

// ---------------- smem layout of main kernel ----------------
#define ROWB   272
#define TILEB  34816              // 128 * 272
#define SM_X1  0
#define SM_X2  TILEB
#define SM_W   (2 * TILEB)        // + buf*(2*TILEB) ; side0 = WT1, side1 = WT2
#define SM_RED (6 * TILEB)        // 128 rows x 3 floats cross-warp partials
#define SM_TOT (6 * TILEB + 128 * 3 * 4)   // 210432 B

// ================= fused prep =================
// Blocks [0, 512): convert x -> bf16 + part2 (fp32, warp-per-8-rows, V amortized).
// Blocks [512, 1024): W transpose+convert (32x32 smem tiles).
__global__ void __launch_bounds__(256) k_prep(const float* __restrict__ x1,
                                              const float* __restrict__ x2,
                                              const float* __restrict__ W1,
                                              const float* __restrict__ W2,
                                              const float* __restrict__ V,
                                              const float* __restrict__ b) {
    __shared__ float t[32][33];
    int bid = blockIdx.x;
    if (bid < 512) {
        int w = threadIdx.x >> 5, lane = threadIdx.x & 31;
        int row0 = (bid * 8 + w) * 8;

        float4 xv1[8], xv2[8];
        #pragma unroll
        for (int r = 0; r < 8; r++) {
            xv1[r] = __ldg(reinterpret_cast<const float4*>(x1 + (size_t)(row0 + r) * DDIM) + lane);
            xv2[r] = __ldg(reinterpret_cast<const float4*>(x2 + (size_t)(row0 + r) * DDIM) + lane);
            {
                __nv_bfloat162 lo = __floats2bfloat162_rn(xv1[r].x, xv1[r].y);
                __nv_bfloat162 hi = __floats2bfloat162_rn(xv1[r].z, xv1[r].w);
                uint2 pk;
                pk.x = *reinterpret_cast<uint32_t*>(&lo);
                pk.y = *reinterpret_cast<uint32_t*>(&hi);
                reinterpret_cast<uint2*>(g_Xb1 + (size_t)(row0 + r) * DDIM)[lane] = pk;
            }
            {
                __nv_bfloat162 lo = __floats2bfloat162_rn(xv2[r].x, xv2[r].y);
                __nv_bfloat162 hi = __floats2bfloat162_rn(xv2[r].z, xv2[r].w);
                uint2 pk;
                pk.x = *reinterpret_cast<uint32_t*>(&lo);
                pk.y = *reinterpret_cast<uint32_t*>(&hi);
                reinterpret_cast<uint2*>(g_Xb2 + (size_t)(row0 + r) * DDIM)[lane] = pk;
            }
        }

        #pragma unroll
        for (int k = 0; k < KHEADS; k++) {
            float4 w1 = __ldg(reinterpret_cast<const float4*>(V + k * 256) + lane);
            float4 w2 = __ldg(reinterpret_cast<const float4*>(V + k * 256 + 128) + lane);
            float a[8];
            #pragma unroll
            for (int r = 0; r < 8; r++) {
                float s = xv1[r].x * w1.x;
                s = fmaf(xv1[r].y, w1.y, s);
                s = fmaf(xv1[r].z, w1.z, s);
                s = fmaf(xv1[r].w, w1.w, s);
                s = fmaf(xv2[r].x, w2.x, s);
                s = fmaf(xv2[r].y, w2.y, s);
                s = fmaf(xv2[r].z, w2.z, s);
                s = fmaf(xv2[r].w, w2.w, s);
                a[r] = s;
            }
            // full butterfly: every a[r] becomes warp-uniform; lane i emits row i's value
            #pragma unroll
            for (int m = 16; m >= 1; m >>= 1) {
                #pragma unroll
                for (int r = 0; r < 8; r++) a[r] += __shfl_xor_sync(0xFFFFFFFFu, a[r], m);
            }
            if (lane < 8) g_P2[k * NTOK + row0 + lane] = a[lane] + __ldg(&b[k]);
        }
    } else {
        int idx = bid - 512;                 // flatten of (x:4, y:8, z:16)
        int k = idx >> 5;
        int rem = idx & 31;
        int dtx = rem & 3;
        int y = (rem >> 2) & 7;
        int which = y >> 2;
        int ety = y & 3;
        int tx = threadIdx.x & 31, ty = threadIdx.x >> 5;
        const float* src = which ? W2 : W1;
        __nv_bfloat16* dst = which ? g_Wb2 : g_Wb1;
        #pragma unroll
        for (int r = 0; r < 32; r += 8) {
            int d = dtx * 32 + ty + r;
            int e = ety * 32 + tx;
            t[ty + r][tx] = src[k * 16384 + d * 128 + e];
        }
        __syncthreads();
        #pragma unroll
        for (int r = 0; r < 32; r += 8) {
            int e = ety * 32 + ty + r;
            int d = dtx * 32 + tx;
            dst[k * 16384 + e * 128 + d] = __float2bfloat16(t[tx][ty + r]);
        }
    }
}

// ================= main HMMA kernel =================
// 256 CTAs x 128 rows; 512 threads (16 warps, 4/SMSP for latency hiding).
// Warp (r = wid&7, c = wid>>3): rows [r*16, r*16+16), e-cols [c*64, c*64+64).
// A-frags (8 ksteps x 2 sides = 64 regs) resident across all 16 heads.

__device__ __forceinline__ void copy_w_buf(uint32_t sb, int buf, int k, int tid) {
    uint32_t dbase = sb + SM_W + (uint32_t)buf * (2 * TILEB);
    const __nv_bfloat16* s1 = g_Wb1 + (size_t)k * 16384;
    const __nv_bfloat16* s2 = g_Wb2 + (size_t)k * 16384;
    #pragma unroll
    for (int it = 0; it < 8; it++) {
        int idx = tid + it * 512;            // 0..4095
        int side = idx >> 11;
        int cc = idx & 2047;
        int row = cc >> 4, ch = cc & 15;
        uint32_t dst = dbase + (uint32_t)side * TILEB + row * ROWB + ch * 16;
        const __nv_bfloat16* src = (side ? s2 : s1) + row * 128 + ch * 8;
        CP_ASYNC16(dst, src);
    }
}

__global__ void __launch_bounds__(512, 1) k_main(float* __restrict__ out) {
    extern __shared__ char smem[];
    uint32_t sb = smem_u32(smem);
    int tid = threadIdx.x, wid = tid >> 5, lid = tid & 31;
    int n0 = blockIdx.x * 128;
    int r = wid & 7, c = wid >> 3;

    // --- X tiles -> smem ---
    {
        const __nv_bfloat16* s1 = g_Xb1 + (size_t)n0 * DDIM;
        const __nv_bfloat16* s2 = g_Xb2 + (size_t)n0 * DDIM;
        #pragma unroll
        for (int it = 0; it < 8; it++) {
            int idx = tid + it * 512;
            int side = idx >> 11;
            int cc = idx & 2047;
            int row = cc >> 4, ch = cc & 15;
            uint32_t dst = sb + (uint32_t)side * TILEB + row * ROWB + ch * 16;
            const __nv_bfloat16* src = (side ? s2 : s1) + row * 128 + ch * 8;
            CP_ASYNC16(dst, src);
        }
        CP_COMMIT();
    }
    copy_w_buf(sb, 0, 0, tid);
    CP_COMMIT();

    CP_WAIT(1);          // X ready
    __syncthreads();

    // --- A fragments: 8 ksteps x 2 sides = 64 regs, resident for all heads ---
    int l15 = lid & 15;
    uint32_t a1f[8][4], a2f[8][4];
    {
        uint32_t aoff = (uint32_t)(r * 16 + l15) * ROWB + (uint32_t)(lid >> 4) * 16;
        #pragma unroll
        for (int s = 0; s < 8; s++) {
            LDSM_X4(a1f[s][0], a1f[s][1], a1f[s][2], a1f[s][3], sb + SM_X1 + aoff + s * 32);
            LDSM_X4(a2f[s][0], a2f[s][1], a2f[s][2], a2f[s][3], sb + SM_X2 + aoff + s * 32);
        }
    }

    uint32_t boff = (uint32_t)(l15 & 7) * ROWB + (uint32_t)(l15 >> 3) * 16
                  + (uint32_t)c * 64 * ROWB;
    float* red = reinterpret_cast<float*>(smem + SM_RED);

    for (int k = 0; k < KHEADS; k++) {
        if (k < KHEADS - 1) {
            copy_w_buf(sb, (k + 1) & 1, k + 1, tid);
            CP_COMMIT();
            CP_WAIT(1);      // buf[k&1] ready
        } else {
            CP_WAIT(0);
        }
        __syncthreads();     // W[k] visible; also protects red reuse from prev head

        uint32_t wbase = sb + SM_W + (uint32_t)(k & 1) * (2 * TILEB);
        uint32_t b1 = wbase + boff;
        uint32_t b2 = wbase + TILEB + boff;

        float dot[2] = {0, 0}, s1s[2] = {0, 0}, s2s[2] = {0, 0};

        #pragma unroll
        for (int ecg = 0; ecg < 4; ecg++) {
            float c1[2][4] = {{0, 0, 0, 0}, {0, 0, 0, 0}};
            float c2[2][4] = {{0, 0, 0, 0}, {0, 0, 0, 0}};
            #pragma unroll
            for (int s = 0; s < 8; s++) {
                #pragma unroll
                for (int ec = 0; ec < 2; ec++) {
                    uint32_t po = (uint32_t)((ecg * 2 + ec) * (8 * ROWB) + s * 32);
                    uint32_t u0, u1, v0, v1;
                    LDSM_X2(u0, u1, b1 + po);
                    LDSM_X2(v0, v1, b2 + po);
                    MMA_BF16(c1[ec], a1f[s], u0, u1);
                    MMA_BF16(c2[ec], a2f[s], v0, v1);
                }
            }
            #pragma unroll
            for (int ec = 0; ec < 2; ec++) {
                dot[0] = fmaf(c1[ec][0], c2[ec][0], dot[0]);
                dot[0] = fmaf(c1[ec][1], c2[ec][1], dot[0]);
                dot[1] = fmaf(c1[ec][2], c2[ec][2], dot[1]);
                dot[1] = fmaf(c1[ec][3], c2[ec][3], dot[1]);
                s1s[0] = fmaf(c1[ec][0], c1[ec][0], s1s[0]);
                s1s[0] = fmaf(c1[ec][1], c1[ec][1], s1s[0]);
                s1s[1] = fmaf(c1[ec][2], c1[ec][2], s1s[1]);
                s1s[1] = fmaf(c1[ec][3], c1[ec][3], s1s[1]);
                s2s[0] = fmaf(c2[ec][0], c2[ec][0], s2s[0]);
                s2s[0] = fmaf(c2[ec][1], c2[ec][1], s2s[0]);
                s2s[1] = fmaf(c2[ec][2], c2[ec][2], s2s[1]);
                s2s[1] = fmaf(c2[ec][3], c2[ec][3], s2s[1]);
            }
        }

        // quad reduce (8 cols live across the 4 lanes of each quad)
        #pragma unroll
        for (int msk = 1; msk <= 2; msk <<= 1) {
            #pragma unroll
            for (int h = 0; h < 2; h++) {
                dot[h] += __shfl_xor_sync(0xFFFFFFFFu, dot[h], msk);
                s1s[h] += __shfl_xor_sync(0xFFFFFFFFu, s1s[h], msk);
                s2s[h] += __shfl_xor_sync(0xFFFFFFFFu, s2s[h], msk);
            }
        }

        // cross-warp (e-halves) combine via smem
        if (c == 1 && (lid & 3) == 0) {
            int g = lid >> 2;
            #pragma unroll
            for (int h = 0; h < 2; h++) {
                int rr = r * 16 + h * 8 + g;
                red[rr * 3 + 0] = dot[h];
                red[rr * 3 + 1] = s1s[h];
                red[rr * 3 + 2] = s2s[h];
            }
        }
        __syncthreads();
        if (c == 0 && (lid & 3) == 0) {
            int g = lid >> 2;
            #pragma unroll
            for (int h = 0; h < 2; h++) {
                int rr = r * 16 + h * 8 + g;
                int n = n0 + rr;
                float D = dot[h] + red[rr * 3 + 0];
                float A = s1s[h] + red[rr * 3 + 1];
                float B = s2s[h] + red[rr * 3 + 2];
                float v = D / (fmaxf(sqrtf(A), 1e-8f) * fmaxf(sqrtf(B), 1e-8f))
                        + g_P2[k * NTOK + n];
                out[(size_t)n * KHEADS + k] = fmaxf(v, 0.f);
            }
        }
    }
}

// ================= launch =================
extern "C" void kernel_launch(void* const* d_in, const int* in_sizes, int n_in,
                              void* d_out, int out_size) {
    const float* x1 = (const float*)d_in[0];
    const float* x2 = (const float*)d_in[1];
    const float* W1 = (const float*)d_in[2];
    const float* W2 = (const float*)d_in[3];
    const float* V  = (const float*)d_in[4];
    const float* b  = (const float*)d_in[5];
    float* out = (float*)d_out;

    k_prep<<<1024, 256>>>(x1, x2, W1, W2, V, b);

    cudaFuncSetAttribute(k_main, cudaFuncAttributeMaxDynamicSharedMemorySize, SM_TOT);
    k_main<<<NTOK / 128, 512, SM_TOT>>>(out);
}